// round 7
// baseline (speedup 1.0000x reference)
#include <cuda_runtime.h>
#include <cstdint>
#include <math.h>

// ---------------------------------------------------------------------------
// GigaMesher9000 round 6 (round 5 + compile fix: <cstdint>).
//   guard1 (no output-ReLU crossing): out = base + ((s.*p)@M)*invc   (exact)
//   guard2 (|g|*invc provably < 2e-4 * min|base|): out = base (const fill)
// guard2 bound: |g_k| = |sum_o sp_o*M_ok| <= max|M| * max_row sum_o|sp_o|.
// Modes: 2 = const fill (bulk-copy), 1 = linear recompute, 0 = exact MLP.
// pass1: pure reduction; packed fp32x2 everywhere; weights pre-duplicated in
// smem (no ALU dup movs); block 0 of pass1 does weight-constant setup
// concurrently. Accumulator zeroing happens at the END (in pass2), so state
// is already zeroed when the next replay's pass1 runs.
// ---------------------------------------------------------------------------

#define MAXN   2000000
#define P1THR  128
#define P1BLK  444          // 148 SMs * 3 (row blocks; +1 setup block)
#define P2THR  256
#define P2BLK  592
#define CHUNKB 12288        // bulk-fill chunk: multiple of 48 and 16
#define CHUNKF (CHUNKB / 4)

typedef unsigned long long ull;

// ---- packed f32x2 helpers --------------------------------------------------
__device__ __forceinline__ ull pk2(float lo, float hi) {
    ull r; asm("mov.b64 %0,{%1,%2};" : "=l"(r) : "f"(lo), "f"(hi)); return r;
}
__device__ __forceinline__ void upk2(ull v, float& lo, float& hi) {
    asm("mov.b64 {%0,%1},%2;" : "=f"(lo), "=f"(hi) : "l"(v));
}
__device__ __forceinline__ ull fma2(ull a, ull b, ull c) {
    ull d; asm("fma.rn.f32x2 %0,%1,%2,%3;" : "=l"(d) : "l"(a), "l"(b), "l"(c)); return d;
}
__device__ __forceinline__ ull mul2(ull a, ull b) {
    ull d; asm("mul.rn.f32x2 %0,%1,%2;" : "=l"(d) : "l"(a), "l"(b)); return d;
}
__device__ __forceinline__ ull add2(ull a, ull b) {
    ull d; asm("add.rn.f32x2 %0,%1,%2;" : "=l"(d) : "l"(a), "l"(b)); return d;
}
__device__ __forceinline__ ull relu2(ull v) {
    float a, b; upk2(v, a, b);
    return pk2(fmaxf(a, 0.f), fmaxf(b, 0.f));
}

// ---- device-global accumulators / constants -------------------------------
__device__ double        g_ss;             // zero-init at load; re-zeroed in pass2
__device__ double        g_pp;
__device__ unsigned int  g_rowmax_bits;
__device__ float         g_M[30];          // [10][3]  (for mode-1 fallback)
__device__ float         g_base[3];
__device__ float         g_minabs_ob1;
__device__ float         g_maxabs_ow1;
__device__ float         g_maxabsM;
__device__ float         g_minabs_base;
__device__ int           g_mode;
__device__ float         g_invc;

// ---------------------------------------------------------------------------
// Pass 1. Block 0 = weight-constant setup (concurrent with row blocks).
// Row blocks: grid-stride over quads (4 rows/thread/iter), packed fp32x2.
// ---------------------------------------------------------------------------
__global__ void __launch_bounds__(P1THR, 3)
k_pass1(const float* __restrict__ x,
        const float* __restrict__ sw1, const float* __restrict__ sb1,
        const float* __restrict__ sw2, const float* __restrict__ sb2,
        const float* __restrict__ pw1, const float* __restrict__ pb1,
        const float* __restrict__ pw2, const float* __restrict__ pb2,
        const float* __restrict__ ow1, const float* __restrict__ ob1,
        const float* __restrict__ ow2, const float* __restrict__ ob2,
        int n)
{
    int tid = threadIdx.x;

    if (blockIdx.x == 0) {
        // ---------------- setup block (no row work) ----------------
        __shared__ float aM[30], bs[3];
        if (tid < 30) {                    // M[i][k] + |M| tracking
            int i = tid / 3, k = tid % 3;
            float acc = 0.f;
            for (int j = 0; j < 100; j++) {
                float o = ob1[j];
                if (o > 0.f) acc = fmaf(ow1[i * 100 + j], ow2[j * 3 + k], acc);
            }
            g_M[tid] = acc;
            aM[tid] = fabsf(acc);
        } else if (tid < 33) {             // base[k]
            int k = tid - 30;
            float acc = ob2[k];
            for (int j = 0; j < 100; j++)
                acc = fmaf(fmaxf(ob1[j], 0.f), ow2[j * 3 + k], acc);
            g_base[k] = acc;
            bs[k] = fabsf(acc);
        }
        if (tid >= 64 && tid < 96) {       // max|ow1|
            int lane = tid - 64;
            float m = 0.f;
            for (int j = lane; j < 1000; j += 32) m = fmaxf(m, fabsf(ow1[j]));
            #pragma unroll
            for (int o = 16; o > 0; o >>= 1)
                m = fmaxf(m, __shfl_down_sync(0xffffffffu, m, o));
            if (lane == 0) g_maxabs_ow1 = m;
        }
        if (tid >= 96) {                   // min|ob1|
            int lane = tid - 96;
            float m = 3.0e38f;
            for (int j = lane; j < 100; j += 32) m = fminf(m, fabsf(ob1[j]));
            #pragma unroll
            for (int o = 16; o > 0; o >>= 1)
                m = fminf(m, __shfl_down_sync(0xffffffffu, m, o));
            if (lane == 0) g_minabs_ob1 = m;
        }
        __syncthreads();
        if (tid == 0) {
            float mm = 0.f;
            #pragma unroll
            for (int i = 0; i < 30; i++) mm = fmaxf(mm, aM[i]);
            g_maxabsM = mm;
            g_minabs_base = fminf(bs[0], fminf(bs[1], bs[2]));
        }
        return;
    }

    // ---------------- row blocks ----------------
    // Packed duplicated weights:
    //  L1S/L1P [40] ull : h*4 + {wx,wy,wz,b}  each (w,w)
    //  L2S/L2P [120] ull: o*12 + {w0..w9, b, 0} each (w,w)
    __shared__ __align__(16) ull L1S[40], L1P[40], L2S[120], L2P[120];

    for (int i = tid; i < 80; i += P1THR) {
        if (i < 40) {
            int h = i >> 2, c = i & 3;
            float w = (c < 3) ? sw1[c * 10 + h] : sb1[h];
            L1S[i] = pk2(w, w);
        } else {
            int j = i - 40, h = j >> 2, c = j & 3;
            float w = (c < 3) ? pw1[c * 10 + h] : pb1[h];
            L1P[j] = pk2(w, w);
        }
    }
    for (int i = tid; i < 240; i += P1THR) {
        if (i < 120) {
            int o = i / 12, c = i - o * 12;
            float w = (c < 10) ? sw2[c * 10 + o] : ((c == 10) ? sb2[o] : 0.f);
            L2S[i] = pk2(w, w);
        } else {
            int j = i - 120, o = j / 12, c = j - o * 12;
            float w = (c < 10) ? pw2[c * 10 + o] : ((c == 10) ? pb2[o] : 0.f);
            L2P[j] = pk2(w, w);
        }
    }
    __syncthreads();

    float lss = 0.f, lpp = 0.f, lmax = 0.f;

    int nquad  = n >> 2;                          // full quads
    int qstart = (blockIdx.x - 1) * P1THR + tid;
    int qstep  = (gridDim.x - 1) * P1THR;
    const ulonglong2* L1Sv = (const ulonglong2*)L1S;
    const ulonglong2* L1Pv = (const ulonglong2*)L1P;
    const ull kAbs = 0x7fffffff7fffffffULL;

    for (int q = qstart; q < nquad; q += qstep) {
        int r0 = q * 4;
        const float4* xv = (const float4*)(x + (size_t)r0 * 6);
        float4 X0 = xv[0], X1 = xv[1], X2 = xv[2], X3 = xv[3], X4 = xv[4], X5 = xv[5];

        ull xs0a = pk2(X0.x, X1.z), xs1a = pk2(X0.y, X1.w), xs2a = pk2(X0.z, X2.x);
        ull xs0b = pk2(X3.x, X4.z), xs1b = pk2(X3.y, X4.w), xs2b = pk2(X3.z, X5.x);
        ull xp0a = pk2(X0.w, X2.y), xp1a = pk2(X1.x, X2.z), xp2a = pk2(X1.y, X2.w);
        ull xp0b = pk2(X3.w, X5.y), xp1b = pk2(X4.x, X5.z), xp2b = pk2(X4.y, X5.w);

        ull hs0[10], hs1[10], hp0[10], hp1[10];
        #pragma unroll
        for (int h = 0; h < 10; h++) {
            ulonglong2 w01 = L1Sv[h * 2], w23 = L1Sv[h * 2 + 1];
            hs0[h] = relu2(fma2(xs2a, w23.x, fma2(xs1a, w01.y, fma2(xs0a, w01.x, w23.y))));
            hs1[h] = relu2(fma2(xs2b, w23.x, fma2(xs1b, w01.y, fma2(xs0b, w01.x, w23.y))));
            ulonglong2 u01 = L1Pv[h * 2], u23 = L1Pv[h * 2 + 1];
            hp0[h] = relu2(fma2(xp2a, u23.x, fma2(xp1a, u01.y, fma2(xp0a, u01.x, u23.y))));
            hp1[h] = relu2(fma2(xp2b, u23.x, fma2(xp1b, u01.y, fma2(xp0b, u01.x, u23.y))));
        }

        ull lss2 = 0ull, lpp2 = 0ull, rs0 = 0ull, rs1 = 0ull;

        #pragma unroll 2
        for (int o = 0; o < 10; o++) {
            const ulonglong2* av = (const ulonglong2*)(L2S + o * 12);
            ulonglong2 a0 = av[0], a1 = av[1], a2 = av[2], a3 = av[3], a4 = av[4], a5 = av[5];
            ull sa0 = a5.x, sa1 = a5.x;
            sa0 = fma2(hs0[0], a0.x, sa0); sa1 = fma2(hs1[0], a0.x, sa1);
            sa0 = fma2(hs0[1], a0.y, sa0); sa1 = fma2(hs1[1], a0.y, sa1);
            sa0 = fma2(hs0[2], a1.x, sa0); sa1 = fma2(hs1[2], a1.x, sa1);
            sa0 = fma2(hs0[3], a1.y, sa0); sa1 = fma2(hs1[3], a1.y, sa1);
            sa0 = fma2(hs0[4], a2.x, sa0); sa1 = fma2(hs1[4], a2.x, sa1);
            sa0 = fma2(hs0[5], a2.y, sa0); sa1 = fma2(hs1[5], a2.y, sa1);
            sa0 = fma2(hs0[6], a3.x, sa0); sa1 = fma2(hs1[6], a3.x, sa1);
            sa0 = fma2(hs0[7], a3.y, sa0); sa1 = fma2(hs1[7], a3.y, sa1);
            sa0 = fma2(hs0[8], a4.x, sa0); sa1 = fma2(hs1[8], a4.x, sa1);
            sa0 = fma2(hs0[9], a4.y, sa0); sa1 = fma2(hs1[9], a4.y, sa1);

            const ulonglong2* bv = (const ulonglong2*)(L2P + o * 12);
            ulonglong2 b0 = bv[0], b1 = bv[1], b2 = bv[2], b3 = bv[3], b4 = bv[4], b5 = bv[5];
            ull pa0 = b5.x, pa1 = b5.x;
            pa0 = fma2(hp0[0], b0.x, pa0); pa1 = fma2(hp1[0], b0.x, pa1);
            pa0 = fma2(hp0[1], b0.y, pa0); pa1 = fma2(hp1[1], b0.y, pa1);
            pa0 = fma2(hp0[2], b1.x, pa0); pa1 = fma2(hp1[2], b1.x, pa1);
            pa0 = fma2(hp0[3], b1.y, pa0); pa1 = fma2(hp1[3], b1.y, pa1);
            pa0 = fma2(hp0[4], b2.x, pa0); pa1 = fma2(hp1[4], b2.x, pa1);
            pa0 = fma2(hp0[5], b2.y, pa0); pa1 = fma2(hp1[5], b2.y, pa1);
            pa0 = fma2(hp0[6], b3.x, pa0); pa1 = fma2(hp1[6], b3.x, pa1);
            pa0 = fma2(hp0[7], b3.y, pa0); pa1 = fma2(hp1[7], b3.y, pa1);
            pa0 = fma2(hp0[8], b4.x, pa0); pa1 = fma2(hp1[8], b4.x, pa1);
            pa0 = fma2(hp0[9], b4.y, pa0); pa1 = fma2(hp1[9], b4.y, pa1);

            lss2 = fma2(sa0, sa0, lss2); lss2 = fma2(sa1, sa1, lss2);
            lpp2 = fma2(pa0, pa0, lpp2); lpp2 = fma2(pa1, pa1, lpp2);
            ull sp0 = mul2(sa0, pa0), sp1 = mul2(sa1, pa1);
            rs0 = add2(rs0, sp0 & kAbs);
            rs1 = add2(rs1, sp1 & kAbs);
        }

        float a, b;
        upk2(lss2, a, b); lss += a + b;
        upk2(lpp2, a, b); lpp += a + b;
        upk2(rs0, a, b);  lmax = fmaxf(lmax, fmaxf(a, b));
        upk2(rs1, a, b);  lmax = fmaxf(lmax, fmaxf(a, b));
    }

    // scalar tail rows (n % 4) handled by first threads of block 1
    int tail = n & 3;
    if (blockIdx.x == 1 && tid < tail) {
        int r = (n & ~3) + tid;
        float xs[6];
        #pragma unroll
        for (int j = 0; j < 6; j++) xs[j] = x[(size_t)r * 6 + j];
        const float* L1Sf = (const float*)L1S;
        const float* L1Pf = (const float*)L1P;
        const float* L2Sf = (const float*)L2S;
        const float* L2Pf = (const float*)L2P;
        float h1s[10], h1p[10];
        #pragma unroll
        for (int h = 0; h < 10; h++) {
            h1s[h] = fmaxf(fmaf(xs[2], L1Sf[(h*4+2)*2], fmaf(xs[1], L1Sf[(h*4+1)*2],
                     fmaf(xs[0], L1Sf[(h*4+0)*2], L1Sf[(h*4+3)*2]))), 0.f);
            h1p[h] = fmaxf(fmaf(xs[5], L1Pf[(h*4+2)*2], fmaf(xs[4], L1Pf[(h*4+1)*2],
                     fmaf(xs[3], L1Pf[(h*4+0)*2], L1Pf[(h*4+3)*2]))), 0.f);
        }
        float rsum = 0.f;
        #pragma unroll 2
        for (int o = 0; o < 10; o++) {
            float sa = L2Sf[(o*12+10)*2], pa = L2Pf[(o*12+10)*2];
            #pragma unroll
            for (int h = 0; h < 10; h++) {
                sa = fmaf(h1s[h], L2Sf[(o*12+h)*2], sa);
                pa = fmaf(h1p[h], L2Pf[(o*12+h)*2], pa);
            }
            lss = fmaf(sa, sa, lss);
            lpp = fmaf(pa, pa, lpp);
            rsum += fabsf(sa * pa);
        }
        lmax = fmaxf(lmax, rsum);
    }

    // ---- reduction ----
    #pragma unroll
    for (int o = 16; o > 0; o >>= 1) {
        lss += __shfl_down_sync(0xffffffffu, lss, o);
        lpp += __shfl_down_sync(0xffffffffu, lpp, o);
        lmax = fmaxf(lmax, __shfl_down_sync(0xffffffffu, lmax, o));
    }
    __shared__ float rs_[4], rp_[4], rm_[4];
    int wid = tid >> 5, lane = tid & 31;
    if (lane == 0) { rs_[wid] = lss; rp_[wid] = lpp; rm_[wid] = lmax; }
    __syncthreads();
    if (tid == 0) {
        float sA = 0.f, sB = 0.f, sM = 0.f;
        #pragma unroll
        for (int w = 0; w < P1THR / 32; w++) {
            sA += rs_[w]; sB += rp_[w]; sM = fmaxf(sM, rm_[w]);
        }
        atomicAdd(&g_ss, (double)sA);
        atomicAdd(&g_pp, (double)sB);
        atomicMax(&g_rowmax_bits, __float_as_uint(sM));
    }
}

// ---------------------------------------------------------------------------
__global__ void k_mid()
{
    float snorm = sqrtf((float)g_ss);
    float pnorm = sqrtf((float)g_pp);
    float c = snorm * pnorm;
    float invc = (c > 0.f) ? (1.0f / c) : 0.0f;
    g_invc = invc;
    float rowmax = __uint_as_float(g_rowmax_bits);
    float bound1 = rowmax * invc * g_maxabs_ow1;        // >= max_j |v_j|
    int f1 = (c > 0.f && g_minabs_ob1 > 2.0f * bound1);
    float gbound = g_maxabsM * rowmax * invc;           // >= max |g_k|*invc
    int f2 = f1 && (gbound < 2.0e-4f * g_minabs_base);
    g_mode = f2 ? 2 : (f1 ? 1 : 0);
}

// ---------------------------------------------------------------------------
// Pass 2: mode 2 -> bulk-copy const fill; mode 1/0 -> compute fallback.
// Also re-zeroes the accumulators for the next replay.
// ---------------------------------------------------------------------------
__global__ void __launch_bounds__(P2THR)
k_pass2(const float* __restrict__ x,
        const float* __restrict__ sw1, const float* __restrict__ sb1,
        const float* __restrict__ sw2, const float* __restrict__ sb2,
        const float* __restrict__ pw1, const float* __restrict__ pb1,
        const float* __restrict__ pw2, const float* __restrict__ pb2,
        const float* __restrict__ ow1, const float* __restrict__ ob1,
        const float* __restrict__ ow2, const float* __restrict__ ob2,
        float* __restrict__ out, int n)
{
    int tid = threadIdx.x;
    if (blockIdx.x == 0 && tid == 0) {          // reset accums for next replay
        g_ss = 0.0; g_pp = 0.0; g_rowmax_bits = 0u;
    }
    int mode = g_mode;

    if (mode == 2) {
        // ------- constant fill via cp.async.bulk shared -> global -------
        __shared__ __align__(16) float patbuf[CHUNKF];
        float b0 = g_base[0], b1 = g_base[1], b2 = g_base[2];
        float bb[3] = {b0, b1, b2};
        for (int i = tid; i < CHUNKF; i += P2THR) patbuf[i] = bb[i % 3];
        __syncthreads();

        size_t total  = (size_t)n * 3;               // floats
        size_t nchunk = (total * 4) / CHUNKB;        // full chunks
        if (tid == 0) {
            asm volatile("fence.proxy.async;" ::: "memory");
            unsigned int saddr;
            asm("{ .reg .u64 t; cvta.to.shared.u64 t, %1; cvt.u32.u64 %0, t; }"
                : "=r"(saddr) : "l"(patbuf));
            for (size_t c = blockIdx.x; c < nchunk; c += gridDim.x) {
                float* dst = out + c * CHUNKF;
                asm volatile(
                    "cp.async.bulk.global.shared::cta.bulk_group [%0], [%1], %2;"
                    :: "l"(dst), "r"(saddr), "r"((unsigned int)CHUNKB) : "memory");
            }
            asm volatile("cp.async.bulk.commit_group;" ::: "memory");
            asm volatile("cp.async.bulk.wait_group 0;" ::: "memory");
        }
        if (blockIdx.x == 0) {                       // remainder floats
            for (size_t i = nchunk * CHUNKF + tid; i < total; i += P2THR)
                out[i] = bb[i % 3];
        }
        return;
    }

    // ---------------- fallback: mode 1 linear / mode 0 exact ----------------
    float invc = g_invc;
    __shared__ __align__(16) float A1[40], B1[40], A2s[120], B2s[120], Ms[32];
    __shared__ float OW1[1000], OB1[100], OW2[300];
    for (int i = tid; i < 80; i += P2THR) {
        if (i < 40) { int h = i >> 2, c = i & 3; A1[i] = (c < 3) ? sw1[c * 10 + h] : sb1[h]; }
        else { int j = i - 40, h = j >> 2, c = j & 3; B1[j] = (c < 3) ? pw1[c * 10 + h] : pb1[h]; }
    }
    for (int i = tid; i < 240; i += P2THR) {
        if (i < 120) { int o = i / 12, c = i - o * 12;
            A2s[i] = (c < 10) ? sw2[c * 10 + o] : ((c == 10) ? sb2[o] : 0.f); }
        else { int j = i - 120, o = j / 12, c = j - o * 12;
            B2s[j] = (c < 10) ? pw2[c * 10 + o] : ((c == 10) ? pb2[o] : 0.f); }
    }
    for (int i = tid; i < 32; i += P2THR) Ms[i] = (i < 30) ? g_M[i] : 0.f;
    if (mode == 0) {
        for (int i = tid; i < 1000; i += P2THR) OW1[i] = ow1[i];
        for (int i = tid; i < 100;  i += P2THR) OB1[i] = ob1[i];
        for (int i = tid; i < 300;  i += P2THR) OW2[i] = ow2[i];
    }
    __syncthreads();
    float c0, c1, c2;
    if (mode == 0) { c0 = ob2[0]; c1 = ob2[1]; c2 = ob2[2]; }
    else           { c0 = g_base[0]; c1 = g_base[1]; c2 = g_base[2]; }

    int stride = gridDim.x * blockDim.x;
    for (int r = blockIdx.x * blockDim.x + tid; r < n; r += stride) {
        const float2* xr = reinterpret_cast<const float2*>(x + (size_t)r * 6);
        float2 u0 = xr[0], u1 = xr[1], u2 = xr[2];
        float h1s[10], h1p[10];
        const float4* A1v = (const float4*)A1;
        const float4* B1v = (const float4*)B1;
        #pragma unroll
        for (int h = 0; h < 10; h++) {
            float4 w = A1v[h];
            h1s[h] = fmaxf(fmaf(u1.x, w.z, fmaf(u0.y, w.y, fmaf(u0.x, w.x, w.w))), 0.f);
            float4 u = B1v[h];
            h1p[h] = fmaxf(fmaf(u2.y, u.z, fmaf(u2.x, u.y, fmaf(u1.y, u.x, u.w))), 0.f);
        }
        float sp[10];
        #pragma unroll
        for (int o = 0; o < 10; o++) {
            const float* av = A2s + 12 * o;
            const float* bv = B2s + 12 * o;
            float sa = av[10], pa = bv[10];
            #pragma unroll
            for (int h = 0; h < 10; h++) {
                sa = fmaf(h1s[h], av[h], sa);
                pa = fmaf(h1p[h], bv[h], pa);
            }
            sp[o] = sa * pa;
        }
        if (mode == 1) {
            float a0 = c0, a1 = c1, a2 = c2;
            #pragma unroll
            for (int o = 0; o < 10; o++) {
                float v = sp[o] * invc;
                a0 = fmaf(v, Ms[3 * o + 0], a0);
                a1 = fmaf(v, Ms[3 * o + 1], a1);
                a2 = fmaf(v, Ms[3 * o + 2], a2);
            }
            out[3 * r + 0] = a0; out[3 * r + 1] = a1; out[3 * r + 2] = a2;
        } else {
            float tf[10];
            #pragma unroll
            for (int o = 0; o < 10; o++) tf[o] = sp[o] * invc;
            float a0 = c0, a1 = c1, a2 = c2;
            #pragma unroll 2
            for (int j = 0; j < 100; j++) {
                float hj = OB1[j];
                #pragma unroll
                for (int o = 0; o < 10; o++)
                    hj = fmaf(tf[o], OW1[o * 100 + j], hj);
                hj = fmaxf(hj, 0.f);
                a0 = fmaf(hj, OW2[3 * j + 0], a0);
                a1 = fmaf(hj, OW2[3 * j + 1], a1);
                a2 = fmaf(hj, OW2[3 * j + 2], a2);
            }
            out[3 * r + 0] = a0; out[3 * r + 1] = a1; out[3 * r + 2] = a2;
        }
    }
}

// ---------------------------------------------------------------------------
extern "C" void kernel_launch(void* const* d_in, const int* in_sizes, int n_in,
                              void* d_out, int out_size)
{
    const float* x   = (const float*)d_in[0];
    const float* sw1 = (const float*)d_in[1];
    const float* sb1 = (const float*)d_in[2];
    const float* sw2 = (const float*)d_in[3];
    const float* sb2 = (const float*)d_in[4];
    const float* pw1 = (const float*)d_in[5];
    const float* pb1 = (const float*)d_in[6];
    const float* pw2 = (const float*)d_in[7];
    const float* pb2 = (const float*)d_in[8];
    const float* ow1 = (const float*)d_in[9];
    const float* ob1 = (const float*)d_in[10];
    const float* ow2 = (const float*)d_in[11];
    const float* ob2 = (const float*)d_in[12];
    float* out = (float*)d_out;

    int n = in_sizes[0] / 6;
    if (n > MAXN) n = MAXN;

    int nquad = n >> 2;
    int rowblk = (nquad + P1THR - 1) / P1THR;
    if (rowblk > P1BLK) rowblk = P1BLK;
    if (rowblk < 1) rowblk = 1;

    k_pass1<<<rowblk + 1, P1THR>>>(x, sw1, sb1, sw2, sb2, pw1, pb1, pw2, pb2,
                                   ow1, ob1, ow2, ob2, n);
    k_mid<<<1, 1>>>();
    k_pass2<<<P2BLK, P2THR>>>(x, sw1, sb1, sw2, sb2, pw1, pb1, pw2, pb2,
                              ow1, ob1, ow2, ob2, out, n);
}

// round 8
// speedup vs baseline: 1.2759x; 1.2759x over previous
#include <cuda_runtime.h>
#include <cstdint>
#include <math.h>

// ---------------------------------------------------------------------------
// GigaMesher9000 round 8.
//   guard1 (no output-ReLU crossing): out = base + ((s.*p)@M)*invc   (exact)
//   guard2 (|g|*invc provably < 2e-4 * min|base|): out = base (const fill)
// guard2 bound: |g_k| <= max|M| * max_row sum_o |s_o p_o|.
// Modes: 2 = const fill (bulk-copy), 1 = linear recompute, 0 = exact MLP.
// Round-8: revert pass1 to round-4's proven inner loop (scalar L2 weights +
// ALU dup movs, one quad per thread), keep no-g-store reduction, force
// regs<=128 via launch_bounds(128,4), and fold the mode computation into the
// last-finishing pass1 block (2 total launches).
// ---------------------------------------------------------------------------

#define MAXN   2000000
#define P1THR  128
#define P2THR  256
#define P2BLK  592
#define CHUNKB 12288        // bulk-fill chunk: multiple of 48 and 16
#define CHUNKF (CHUNKB / 4)

typedef unsigned long long ull;

// ---- packed f32x2 helpers --------------------------------------------------
__device__ __forceinline__ ull pk2(float lo, float hi) {
    ull r; asm("mov.b64 %0,{%1,%2};" : "=l"(r) : "f"(lo), "f"(hi)); return r;
}
__device__ __forceinline__ void upk2(ull v, float& lo, float& hi) {
    asm("mov.b64 {%0,%1},%2;" : "=f"(lo), "=f"(hi) : "l"(v));
}
__device__ __forceinline__ ull dup2(float w) {
    ull r; asm("mov.b64 %0,{%1,%1};" : "=l"(r) : "f"(w)); return r;
}
__device__ __forceinline__ ull fma2(ull a, ull b, ull c) {
    ull d; asm("fma.rn.f32x2 %0,%1,%2,%3;" : "=l"(d) : "l"(a), "l"(b), "l"(c)); return d;
}
__device__ __forceinline__ ull mul2(ull a, ull b) {
    ull d; asm("mul.rn.f32x2 %0,%1,%2;" : "=l"(d) : "l"(a), "l"(b)); return d;
}
__device__ __forceinline__ ull add2(ull a, ull b) {
    ull d; asm("add.rn.f32x2 %0,%1,%2;" : "=l"(d) : "l"(a), "l"(b)); return d;
}
__device__ __forceinline__ ull relu2(ull v) {
    float a, b; upk2(v, a, b);
    return pk2(fmaxf(a, 0.f), fmaxf(b, 0.f));
}

// ---- device-global accumulators / constants -------------------------------
__device__ double        g_ss;             // zero at load; re-zeroed by finalize
__device__ double        g_pp;
__device__ unsigned int  g_rowmax_bits;
__device__ unsigned int  g_count;          // block-completion counter
__device__ float         g_M[30];          // [10][3]  (mode-1 fallback)
__device__ float         g_base[3];
__device__ float         g_minabs_ob1;
__device__ float         g_maxabs_ow1;
__device__ float         g_maxabsM;
__device__ float         g_minabs_base;
__device__ int           g_mode;
__device__ float         g_invc;

// ---------------------------------------------------------------------------
// Pass 1. Block 0 = weight-constant setup. Blocks 1..rowblk = one quad/thread.
// Last-finishing block computes mode/invc and resets accumulators.
// ---------------------------------------------------------------------------
__global__ void __launch_bounds__(P1THR, 4)
k_pass1(const float* __restrict__ x,
        const float* __restrict__ sw1, const float* __restrict__ sb1,
        const float* __restrict__ sw2, const float* __restrict__ sb2,
        const float* __restrict__ pw1, const float* __restrict__ pb1,
        const float* __restrict__ pw2, const float* __restrict__ pb2,
        const float* __restrict__ ow1, const float* __restrict__ ob1,
        const float* __restrict__ ow2, const float* __restrict__ ob2,
        int n)
{
    int tid = threadIdx.x;

    if (blockIdx.x == 0) {
        // ---------------- setup block ----------------
        __shared__ float aM[30], bs[3];
        if (tid < 30) {
            int i = tid / 3, k = tid % 3;
            float acc = 0.f;
            for (int j = 0; j < 100; j++) {
                float o = ob1[j];
                if (o > 0.f) acc = fmaf(ow1[i * 100 + j], ow2[j * 3 + k], acc);
            }
            g_M[tid] = acc;
            aM[tid] = fabsf(acc);
        } else if (tid < 33) {
            int k = tid - 30;
            float acc = ob2[k];
            for (int j = 0; j < 100; j++)
                acc = fmaf(fmaxf(ob1[j], 0.f), ow2[j * 3 + k], acc);
            g_base[k] = acc;
            bs[k] = fabsf(acc);
        }
        if (tid >= 64 && tid < 96) {
            int lane = tid - 64;
            float m = 0.f;
            for (int j = lane; j < 1000; j += 32) m = fmaxf(m, fabsf(ow1[j]));
            #pragma unroll
            for (int o = 16; o > 0; o >>= 1)
                m = fmaxf(m, __shfl_down_sync(0xffffffffu, m, o));
            if (lane == 0) g_maxabs_ow1 = m;
        }
        if (tid >= 96) {
            int lane = tid - 96;
            float m = 3.0e38f;
            for (int j = lane; j < 100; j += 32) m = fminf(m, fabsf(ob1[j]));
            #pragma unroll
            for (int o = 16; o > 0; o >>= 1)
                m = fminf(m, __shfl_down_sync(0xffffffffu, m, o));
            if (lane == 0) g_minabs_ob1 = m;
        }
        __syncthreads();
        if (tid == 0) {
            float mm = 0.f;
            #pragma unroll
            for (int i = 0; i < 30; i++) mm = fmaxf(mm, aM[i]);
            g_maxabsM = mm;
            g_minabs_base = fminf(bs[0], fminf(bs[1], bs[2]));

            __threadfence();
            unsigned int old = atomicAdd(&g_count, 1u);
            if (old == gridDim.x - 1) {        // (can't happen unless grid==1)
                g_mode = 0; g_invc = 0.f;
                g_ss = 0.0; g_pp = 0.0; g_rowmax_bits = 0u; g_count = 0u;
                __threadfence();
            }
        }
        return;
    }

    // ---------------- row blocks ----------------
    // A1/B1: layer1 float4 per h {w0,w1,w2,bias}.
    // A2s/B2s: layer2 scalar, o*12 + {w0..w9, bias, pad}.
    __shared__ __align__(16) float A1[40], B1[40], A2s[120], B2s[120];

    for (int i = tid; i < 80; i += P1THR) {
        if (i < 40) {
            int h = i >> 2, c = i & 3;
            A1[i] = (c < 3) ? sw1[c * 10 + h] : sb1[h];
        } else {
            int j = i - 40, h = j >> 2, c = j & 3;
            B1[j] = (c < 3) ? pw1[c * 10 + h] : pb1[h];
        }
    }
    for (int i = tid; i < 240; i += P1THR) {
        if (i < 120) {
            int o = i / 12, c = i - o * 12;
            A2s[i] = (c < 10) ? sw2[c * 10 + o] : ((c == 10) ? sb2[o] : 0.f);
        } else {
            int j = i - 120, o = j / 12, c = j - o * 12;
            B2s[j] = (c < 10) ? pw2[c * 10 + o] : ((c == 10) ? pb2[o] : 0.f);
        }
    }
    __syncthreads();

    float lss = 0.f, lpp = 0.f, lmax = 0.f;

    int nquad = n >> 2;
    int q = (blockIdx.x - 1) * P1THR + tid;

    if (q < nquad) {
        int r0 = q * 4;
        const float4* xv = (const float4*)(x + (size_t)r0 * 6);
        float4 X0 = xv[0], X1 = xv[1], X2 = xv[2], X3 = xv[3], X4 = xv[4], X5 = xv[5];

        // packed inputs: pair a = rows (0,1), pair b = rows (2,3)
        ull xs0a = pk2(X0.x, X1.z), xs1a = pk2(X0.y, X1.w), xs2a = pk2(X0.z, X2.x);
        ull xs0b = pk2(X3.x, X4.z), xs1b = pk2(X3.y, X4.w), xs2b = pk2(X3.z, X5.x);
        ull xp0a = pk2(X0.w, X2.y), xp1a = pk2(X1.x, X2.z), xp2a = pk2(X1.y, X2.w);
        ull xp0b = pk2(X3.w, X5.y), xp1b = pk2(X4.x, X5.z), xp2b = pk2(X4.y, X5.w);

        ull hs0[10], hs1[10], hp0[10], hp1[10];
        const float4* A1v = (const float4*)A1;
        const float4* B1v = (const float4*)B1;
        #pragma unroll
        for (int h = 0; h < 10; h++) {
            float4 w = A1v[h];
            ull wx = dup2(w.x), wy = dup2(w.y), wz = dup2(w.z), wb = dup2(w.w);
            hs0[h] = relu2(fma2(xs2a, wz, fma2(xs1a, wy, fma2(xs0a, wx, wb))));
            hs1[h] = relu2(fma2(xs2b, wz, fma2(xs1b, wy, fma2(xs0b, wx, wb))));
            float4 u = B1v[h];
            ull ux = dup2(u.x), uy = dup2(u.y), uz = dup2(u.z), ub = dup2(u.w);
            hp0[h] = relu2(fma2(xp2a, uz, fma2(xp1a, uy, fma2(xp0a, ux, ub))));
            hp1[h] = relu2(fma2(xp2b, uz, fma2(xp1b, uy, fma2(xp0b, ux, ub))));
        }

        ull lss2 = 0ull, lpp2 = 0ull, rs0 = 0ull, rs1 = 0ull;
        const ull kAbs = 0x7fffffff7fffffffULL;

        #pragma unroll 2
        for (int o = 0; o < 10; o++) {
            const float4* av = (const float4*)(A2s + 12 * o);
            float4 a0 = av[0], a1 = av[1], a2 = av[2];
            ull sa0 = dup2(a2.z), sa1 = sa0;
            ull W;
            W = dup2(a0.x); sa0 = fma2(hs0[0], W, sa0); sa1 = fma2(hs1[0], W, sa1);
            W = dup2(a0.y); sa0 = fma2(hs0[1], W, sa0); sa1 = fma2(hs1[1], W, sa1);
            W = dup2(a0.z); sa0 = fma2(hs0[2], W, sa0); sa1 = fma2(hs1[2], W, sa1);
            W = dup2(a0.w); sa0 = fma2(hs0[3], W, sa0); sa1 = fma2(hs1[3], W, sa1);
            W = dup2(a1.x); sa0 = fma2(hs0[4], W, sa0); sa1 = fma2(hs1[4], W, sa1);
            W = dup2(a1.y); sa0 = fma2(hs0[5], W, sa0); sa1 = fma2(hs1[5], W, sa1);
            W = dup2(a1.z); sa0 = fma2(hs0[6], W, sa0); sa1 = fma2(hs1[6], W, sa1);
            W = dup2(a1.w); sa0 = fma2(hs0[7], W, sa0); sa1 = fma2(hs1[7], W, sa1);
            W = dup2(a2.x); sa0 = fma2(hs0[8], W, sa0); sa1 = fma2(hs1[8], W, sa1);
            W = dup2(a2.y); sa0 = fma2(hs0[9], W, sa0); sa1 = fma2(hs1[9], W, sa1);

            const float4* bv = (const float4*)(B2s + 12 * o);
            float4 b0 = bv[0], b1 = bv[1], b2 = bv[2];
            ull pa0 = dup2(b2.z), pa1 = pa0;
            W = dup2(b0.x); pa0 = fma2(hp0[0], W, pa0); pa1 = fma2(hp1[0], W, pa1);
            W = dup2(b0.y); pa0 = fma2(hp0[1], W, pa0); pa1 = fma2(hp1[1], W, pa1);
            W = dup2(b0.z); pa0 = fma2(hp0[2], W, pa0); pa1 = fma2(hp1[2], W, pa1);
            W = dup2(b0.w); pa0 = fma2(hp0[3], W, pa0); pa1 = fma2(hp1[3], W, pa1);
            W = dup2(b1.x); pa0 = fma2(hp0[4], W, pa0); pa1 = fma2(hp1[4], W, pa1);
            W = dup2(b1.y); pa0 = fma2(hp0[5], W, pa0); pa1 = fma2(hp1[5], W, pa1);
            W = dup2(b1.z); pa0 = fma2(hp0[6], W, pa0); pa1 = fma2(hp1[6], W, pa1);
            W = dup2(b1.w); pa0 = fma2(hp0[7], W, pa0); pa1 = fma2(hp1[7], W, pa1);
            W = dup2(b2.x); pa0 = fma2(hp0[8], W, pa0); pa1 = fma2(hp1[8], W, pa1);
            W = dup2(b2.y); pa0 = fma2(hp0[9], W, pa0); pa1 = fma2(hp1[9], W, pa1);

            lss2 = fma2(sa0, sa0, lss2); lss2 = fma2(sa1, sa1, lss2);
            lpp2 = fma2(pa0, pa0, lpp2); lpp2 = fma2(pa1, pa1, lpp2);
            ull sp0 = mul2(sa0, pa0), sp1 = mul2(sa1, pa1);
            rs0 = add2(rs0, sp0 & kAbs);
            rs1 = add2(rs1, sp1 & kAbs);
        }

        float a, b;
        upk2(lss2, a, b); lss = a + b;
        upk2(lpp2, a, b); lpp = a + b;
        upk2(rs0, a, b);  lmax = fmaxf(a, b);
        upk2(rs1, a, b);  lmax = fmaxf(lmax, fmaxf(a, b));
    }

    // scalar tail rows (n % 4) in block 1
    int tail = n & 3;
    if (blockIdx.x == 1 && tid < tail) {
        int r = (n & ~3) + tid;
        float xs[6];
        #pragma unroll
        for (int j = 0; j < 6; j++) xs[j] = x[(size_t)r * 6 + j];
        float h1s[10], h1p[10];
        const float4* A1v = (const float4*)A1;
        const float4* B1v = (const float4*)B1;
        #pragma unroll
        for (int h = 0; h < 10; h++) {
            float4 w = A1v[h];
            h1s[h] = fmaxf(fmaf(xs[2], w.z, fmaf(xs[1], w.y, fmaf(xs[0], w.x, w.w))), 0.f);
            float4 u = B1v[h];
            h1p[h] = fmaxf(fmaf(xs[5], u.z, fmaf(xs[4], u.y, fmaf(xs[3], u.x, u.w))), 0.f);
        }
        float rsum = 0.f;
        #pragma unroll 2
        for (int o = 0; o < 10; o++) {
            const float* av = A2s + 12 * o;
            const float* bv = B2s + 12 * o;
            float sa = av[10], pa = bv[10];
            #pragma unroll
            for (int h = 0; h < 10; h++) {
                sa = fmaf(h1s[h], av[h], sa);
                pa = fmaf(h1p[h], bv[h], pa);
            }
            lss = fmaf(sa, sa, lss);
            lpp = fmaf(pa, pa, lpp);
            rsum += fabsf(sa * pa);
        }
        lmax = fmaxf(lmax, rsum);
    }

    // ---- reduction + last-block finalize ----
    #pragma unroll
    for (int o = 16; o > 0; o >>= 1) {
        lss += __shfl_down_sync(0xffffffffu, lss, o);
        lpp += __shfl_down_sync(0xffffffffu, lpp, o);
        lmax = fmaxf(lmax, __shfl_down_sync(0xffffffffu, lmax, o));
    }
    __shared__ float rs_[4], rp_[4], rm_[4];
    int wid = tid >> 5, lane = tid & 31;
    if (lane == 0) { rs_[wid] = lss; rp_[wid] = lpp; rm_[wid] = lmax; }
    __syncthreads();
    if (tid == 0) {
        float sA = 0.f, sB = 0.f, sM = 0.f;
        #pragma unroll
        for (int w = 0; w < P1THR / 32; w++) {
            sA += rs_[w]; sB += rp_[w]; sM = fmaxf(sM, rm_[w]);
        }
        atomicAdd(&g_ss, (double)sA);
        atomicAdd(&g_pp, (double)sB);
        atomicMax(&g_rowmax_bits, __float_as_uint(sM));

        __threadfence();
        unsigned int old = atomicAdd(&g_count, 1u);
        if (old == gridDim.x - 1) {
            __threadfence();
            float snorm = sqrtf((float)g_ss);
            float pnorm = sqrtf((float)g_pp);
            float c = snorm * pnorm;
            float invc = (c > 0.f) ? (1.0f / c) : 0.0f;
            g_invc = invc;
            float rowmax = __uint_as_float(g_rowmax_bits);
            float bound1 = rowmax * invc * g_maxabs_ow1;
            int f1 = (c > 0.f && g_minabs_ob1 > 2.0f * bound1);
            float gbound = g_maxabsM * rowmax * invc;
            int f2 = f1 && (gbound < 2.0e-4f * g_minabs_base);
            g_mode = f2 ? 2 : (f1 ? 1 : 0);
            // reset for next replay
            g_ss = 0.0; g_pp = 0.0; g_rowmax_bits = 0u; g_count = 0u;
            __threadfence();
        }
    }
}

// ---------------------------------------------------------------------------
// Pass 2: mode 2 -> bulk-copy const fill; mode 1/0 -> compute fallback.
// ---------------------------------------------------------------------------
__global__ void __launch_bounds__(P2THR)
k_pass2(const float* __restrict__ x,
        const float* __restrict__ sw1, const float* __restrict__ sb1,
        const float* __restrict__ sw2, const float* __restrict__ sb2,
        const float* __restrict__ pw1, const float* __restrict__ pb1,
        const float* __restrict__ pw2, const float* __restrict__ pb2,
        const float* __restrict__ ow1, const float* __restrict__ ob1,
        const float* __restrict__ ow2, const float* __restrict__ ob2,
        float* __restrict__ out, int n)
{
    int tid = threadIdx.x;
    int mode = g_mode;

    if (mode == 2) {
        // ------- constant fill via cp.async.bulk shared -> global -------
        __shared__ __align__(16) float patbuf[CHUNKF];
        float b0 = g_base[0], b1 = g_base[1], b2 = g_base[2];
        float bb[3] = {b0, b1, b2};
        for (int i = tid; i < CHUNKF; i += P2THR) patbuf[i] = bb[i % 3];
        __syncthreads();

        size_t total  = (size_t)n * 3;               // floats
        size_t nchunk = (total * 4) / CHUNKB;        // full chunks
        if (tid == 0) {
            asm volatile("fence.proxy.async;" ::: "memory");
            unsigned int saddr;
            asm("{ .reg .u64 t; cvta.to.shared.u64 t, %1; cvt.u32.u64 %0, t; }"
                : "=r"(saddr) : "l"(patbuf));
            for (size_t c = blockIdx.x; c < nchunk; c += gridDim.x) {
                float* dst = out + c * CHUNKF;
                asm volatile(
                    "cp.async.bulk.global.shared::cta.bulk_group [%0], [%1], %2;"
                    :: "l"(dst), "r"(saddr), "r"((unsigned int)CHUNKB) : "memory");
            }
            asm volatile("cp.async.bulk.commit_group;" ::: "memory");
            asm volatile("cp.async.bulk.wait_group 0;" ::: "memory");
        }
        if (blockIdx.x == 0) {                       // remainder floats
            for (size_t i = nchunk * CHUNKF + tid; i < total; i += P2THR)
                out[i] = bb[i % 3];
        }
        return;
    }

    // ---------------- fallback: mode 1 linear / mode 0 exact ----------------
    float invc = g_invc;
    __shared__ __align__(16) float A1[40], B1[40], A2s[120], B2s[120], Ms[32];
    __shared__ float OW1[1000], OB1[100], OW2[300];
    for (int i = tid; i < 80; i += P2THR) {
        if (i < 40) { int h = i >> 2, c = i & 3; A1[i] = (c < 3) ? sw1[c * 10 + h] : sb1[h]; }
        else { int j = i - 40, h = j >> 2, c = j & 3; B1[j] = (c < 3) ? pw1[c * 10 + h] : pb1[h]; }
    }
    for (int i = tid; i < 240; i += P2THR) {
        if (i < 120) { int o = i / 12, c = i - o * 12;
            A2s[i] = (c < 10) ? sw2[c * 10 + o] : ((c == 10) ? sb2[o] : 0.f); }
        else { int j = i - 120, o = j / 12, c = j - o * 12;
            B2s[j] = (c < 10) ? pw2[c * 10 + o] : ((c == 10) ? pb2[o] : 0.f); }
    }
    for (int i = tid; i < 32; i += P2THR) Ms[i] = (i < 30) ? g_M[i] : 0.f;
    if (mode == 0) {
        for (int i = tid; i < 1000; i += P2THR) OW1[i] = ow1[i];
        for (int i = tid; i < 100;  i += P2THR) OB1[i] = ob1[i];
        for (int i = tid; i < 300;  i += P2THR) OW2[i] = ow2[i];
    }
    __syncthreads();
    float c0, c1, c2;
    if (mode == 0) { c0 = ob2[0]; c1 = ob2[1]; c2 = ob2[2]; }
    else           { c0 = g_base[0]; c1 = g_base[1]; c2 = g_base[2]; }

    int stride = gridDim.x * blockDim.x;
    for (int r = blockIdx.x * blockDim.x + tid; r < n; r += stride) {
        const float2* xr = reinterpret_cast<const float2*>(x + (size_t)r * 6);
        float2 u0 = xr[0], u1 = xr[1], u2 = xr[2];
        float h1s[10], h1p[10];
        const float4* A1v = (const float4*)A1;
        const float4* B1v = (const float4*)B1;
        #pragma unroll
        for (int h = 0; h < 10; h++) {
            float4 w = A1v[h];
            h1s[h] = fmaxf(fmaf(u1.x, w.z, fmaf(u0.y, w.y, fmaf(u0.x, w.x, w.w))), 0.f);
            float4 u = B1v[h];
            h1p[h] = fmaxf(fmaf(u2.y, u.z, fmaf(u2.x, u.y, fmaf(u1.y, u.x, u.w))), 0.f);
        }
        float sp[10];
        #pragma unroll
        for (int o = 0; o < 10; o++) {
            const float* av = A2s + 12 * o;
            const float* bv = B2s + 12 * o;
            float sa = av[10], pa = bv[10];
            #pragma unroll
            for (int h = 0; h < 10; h++) {
                sa = fmaf(h1s[h], av[h], sa);
                pa = fmaf(h1p[h], bv[h], pa);
            }
            sp[o] = sa * pa;
        }
        if (mode == 1) {
            float a0 = c0, a1 = c1, a2 = c2;
            #pragma unroll
            for (int o = 0; o < 10; o++) {
                float v = sp[o] * invc;
                a0 = fmaf(v, Ms[3 * o + 0], a0);
                a1 = fmaf(v, Ms[3 * o + 1], a1);
                a2 = fmaf(v, Ms[3 * o + 2], a2);
            }
            out[3 * r + 0] = a0; out[3 * r + 1] = a1; out[3 * r + 2] = a2;
        } else {
            float tf[10];
            #pragma unroll
            for (int o = 0; o < 10; o++) tf[o] = sp[o] * invc;
            float a0 = c0, a1 = c1, a2 = c2;
            #pragma unroll 2
            for (int j = 0; j < 100; j++) {
                float hj = OB1[j];
                #pragma unroll
                for (int o = 0; o < 10; o++)
                    hj = fmaf(tf[o], OW1[o * 100 + j], hj);
                hj = fmaxf(hj, 0.f);
                a0 = fmaf(hj, OW2[3 * j + 0], a0);
                a1 = fmaf(hj, OW2[3 * j + 1], a1);
                a2 = fmaf(hj, OW2[3 * j + 2], a2);
            }
            out[3 * r + 0] = a0; out[3 * r + 1] = a1; out[3 * r + 2] = a2;
        }
    }
}

// ---------------------------------------------------------------------------
extern "C" void kernel_launch(void* const* d_in, const int* in_sizes, int n_in,
                              void* d_out, int out_size)
{
    const float* x   = (const float*)d_in[0];
    const float* sw1 = (const float*)d_in[1];
    const float* sb1 = (const float*)d_in[2];
    const float* sw2 = (const float*)d_in[3];
    const float* sb2 = (const float*)d_in[4];
    const float* pw1 = (const float*)d_in[5];
    const float* pb1 = (const float*)d_in[6];
    const float* pw2 = (const float*)d_in[7];
    const float* pb2 = (const float*)d_in[8];
    const float* ow1 = (const float*)d_in[9];
    const float* ob1 = (const float*)d_in[10];
    const float* ow2 = (const float*)d_in[11];
    const float* ob2 = (const float*)d_in[12];
    float* out = (float*)d_out;

    int n = in_sizes[0] / 6;
    if (n > MAXN) n = MAXN;

    int nquad  = n >> 2;
    int rowblk = (nquad + P1THR - 1) / P1THR;
    if (rowblk < 1) rowblk = 1;

    k_pass1<<<rowblk + 1, P1THR>>>(x, sw1, sb1, sw2, sb2, pw1, pb1, pw2, pb2,
                                   ow1, ob1, ow2, ob2, n);
    k_pass2<<<P2BLK, P2THR>>>(x, sw1, sb1, sw2, sb2, pw1, pb1, pw2, pb2,
                              ow1, ob1, ow2, ob2, out, n);
}